// round 7
// baseline (speedup 1.0000x reference)
#include <cuda_runtime.h>
#include <cuda_bf16.h>
#include <cstdint>
#include <math.h>

// VectorQuantizer N=65536, D=64, K=512.
// R7: mma.sync (bf16 HMMA, sm_80-portable PTX) screening GEMM in registers
// + deterministic EPS-margin candidate collection + exact fp32 rescore.
// d_out (f32): [0]=loss, [1..ND]=quantized_st, [1+ND]=perplexity, [2+ND..)=idx.

#define D_DIM   64
#define K_CODES 512
#define M_TILE  128
#define TILES   512          // 65536 / 128
#define TPB     256
#define EPS     5e-3f        // >= 2x two-sided worst-case bf16 screen error
#define MAXC    16

typedef unsigned int u32;

__device__ __nv_bfloat16 g_cbb[K_CODES * D_DIM];  // bf16 codebook
__device__ float  g_cnorm[K_CODES];
__device__ int    g_hist[K_CODES];                // reset by vq_final
__device__ double g_sse;                          // reset by vq_final

__device__ __forceinline__ u32 smem_u32(const void* p) {
    u32 a;
    asm("{ .reg .u64 t; cvta.to.shared.u64 t, %1; cvt.u32.u64 %0, t; }"
        : "=r"(a) : "l"(p));
    return a;
}
__device__ __forceinline__ u32 sw128(u32 b) { return b ^ ((b >> 3) & 0x70); }

__device__ __forceinline__ void ldsm_x4(u32& r0, u32& r1, u32& r2, u32& r3, u32 a) {
    asm volatile("ldmatrix.sync.aligned.m8n8.x4.shared.b16 {%0,%1,%2,%3}, [%4];"
                 : "=r"(r0), "=r"(r1), "=r"(r2), "=r"(r3) : "r"(a));
}
__device__ __forceinline__ void ldsm_x2(u32& r0, u32& r1, u32 a) {
    asm volatile("ldmatrix.sync.aligned.m8n8.x2.shared.b16 {%0,%1}, [%2];"
                 : "=r"(r0), "=r"(r1) : "r"(a));
}
__device__ __forceinline__ void mma16816(float& c0, float& c1, float& c2, float& c3,
                                         u32 a0, u32 a1, u32 a2, u32 a3,
                                         u32 b0, u32 b1) {
    asm volatile(
        "mma.sync.aligned.m16n8k16.row.col.f32.bf16.bf16.f32 "
        "{%0,%1,%2,%3}, {%4,%5,%6,%7}, {%8,%9}, {%0,%1,%2,%3};"
        : "+f"(c0), "+f"(c1), "+f"(c2), "+f"(c3)
        : "r"(a0), "r"(a1), "r"(a2), "r"(a3), "r"(b0), "r"(b1));
}

// ---- smem layout (bytes) ----
#define SM_X    0                        // 128*64 f32 = 32768
#define SM_A    32768                    // 128 rows * 128B bf16 (SW128) = 16384
#define SM_B    49152                    // 512 rows * 128B bf16 (SW128) = 65536
#define SM_CN   114688                   // 512 f32 = 2048
#define SM_AN   116736                   // 128 f32 = 512
#define SM_CNT  117248                   // 128 int = 512
#define SM_CAND 117760                   // 128*16 int = 8192
#define SM_RED  125952                   // 8 double = 64
#define SMEM_SZ 126016

// ---------------------------------------------------------------------------
// Prep: bf16 codebook + fp32 norms (warp per code, coalesced).
// ---------------------------------------------------------------------------
__global__ void vq_prep(const float* __restrict__ cb) {
    int gt = blockIdx.x * 256 + threadIdx.x;
    int w = gt >> 5, lane = gt & 31;                 // w = code 0..511
    const float* c = cb + w * D_DIM;
    float v0 = c[lane], v1 = c[lane + 32];
    g_cbb[w * D_DIM + lane]      = __float2bfloat16(v0);
    g_cbb[w * D_DIM + lane + 32] = __float2bfloat16(v1);
    double s = (double)__fmul_rn(v0, v0) + (double)__fmul_rn(v1, v1);
#pragma unroll
    for (int o = 16; o > 0; o >>= 1)
        s += __shfl_xor_sync(0xFFFFFFFFu, s, o);
    if (lane == 0) g_cnorm[w] = (float)s;
}

// Exact fp32 score s = fl( fl(A - 2*dot) + C ), 4-chain fp32 dot
__device__ __forceinline__ float exact_score(const float* __restrict__ cb,
                                             const float4* __restrict__ xr,
                                             float A, float C, int k) {
    const float4* cr = (const float4*)(cb + k * D_DIM);
    float a0 = 0.f, a1 = 0.f, a2 = 0.f, a3 = 0.f;
#pragma unroll
    for (int j = 0; j < D_DIM / 4; j++) {
        float4 cv = cr[j], xv = xr[j];
        a0 = __fmaf_rn(xv.x, cv.x, a0);
        a1 = __fmaf_rn(xv.y, cv.y, a1);
        a2 = __fmaf_rn(xv.z, cv.z, a2);
        a3 = __fmaf_rn(xv.w, cv.w, a3);
    }
    float dot = (a0 + a1) + (a2 + a3);
    return __fadd_rn(__fmaf_rn(-2.f, dot, A), C);
}

__device__ __forceinline__ void push_cand(int* scnt, int* scand, int row,
                                          int col, float t, float& tb) {
    if (t < tb + EPS) {
        int p = atomicAdd(&scnt[row], 1);
        if (p < MAXC) scand[row * MAXC + p] = col;
        if (t < tb) tb = t;
    }
}

// ---------------------------------------------------------------------------
// Main: one CTA per 128-row tile. Screen via HMMA, rescore exactly.
// ---------------------------------------------------------------------------
__global__ __launch_bounds__(TPB, 1)
void vq_main(const float* __restrict__ x, const float* __restrict__ cb,
             float* __restrict__ outq, float* __restrict__ outidx) {
    extern __shared__ char smem[];
    const u32 sb  = smem_u32(smem);
    const int tid = threadIdx.x;
    const int lane = tid & 31;
    const int wrow = (tid >> 5) * 16;               // warp's first local row

    float* sx   = (float*)(smem + SM_X);
    float* scn  = (float*)(smem + SM_CN);
    float* san  = (float*)(smem + SM_AN);
    int*   scnt = (int*)(smem + SM_CNT);
    int*   scand= (int*)(smem + SM_CAND);
    double* sred= (double*)(smem + SM_RED);

    // x tile -> smem (coalesced float4)
    {
        const float4* xs = (const float4*)(x + (size_t)blockIdx.x * M_TILE * D_DIM);
        float4* xd = (float4*)sx;
#pragma unroll
        for (int i = 0; i < 8; i++) xd[tid + 256 * i] = xs[tid + 256 * i];
    }
    // B: bf16 codebook -> smem SW128 (2 rows/thread, 8x uint4 each)
    {
#pragma unroll
        for (int rr = 0; rr < 2; rr++) {
            int row = tid * 2 + rr;
            const uint4* src = (const uint4*)(g_cbb + row * D_DIM);
#pragma unroll
            for (int j = 0; j < 8; j++)
                *(uint4*)(smem + SM_B + sw128(row * 128 + j * 16)) = src[j];
        }
    }
    scn[tid]       = g_cnorm[tid];
    scn[tid + 256] = g_cnorm[tid + 256];
    if (tid < M_TILE) scnt[tid] = 0;
    __syncthreads();

    // A: convert x rows to bf16 SW128 + exact fp32 row norm (threads 0..127)
    if (tid < M_TILE) {
        const float4* xr = (const float4*)sx + tid * 16;
        double sa = 0.0;
#pragma unroll
        for (int j = 0; j < 16; j++) {
            float4 v = xr[j];
            sa += (double)__fmul_rn(v.x, v.x); sa += (double)__fmul_rn(v.y, v.y);
            sa += (double)__fmul_rn(v.z, v.z); sa += (double)__fmul_rn(v.w, v.w);
            __nv_bfloat162 p0 = __floats2bfloat162_rn(v.x, v.y);
            __nv_bfloat162 p1 = __floats2bfloat162_rn(v.z, v.w);
            u32 base = tid * 128 + j * 8;
            *(u32*)(smem + SM_A + sw128(base))     = *(u32*)&p0;
            *(u32*)(smem + SM_A + sw128(base + 4)) = *(u32*)&p1;
        }
        san[tid] = (float)sa;
    }
    __syncthreads();

    // ---- screening GEMM: each warp does rows [wrow, wrow+16) x 512 codes ----
    {
        // A fragments: 4 k-steps, resident (16 regs)
        u32 af[4][4];
        {
            int r    = (lane & 7) + ((lane & 8) ? 8 : 0);
            int half = (lane >> 4) & 1;
            u32 abase = (u32)(wrow + r) * 128 + half * 16;
#pragma unroll
            for (int ks = 0; ks < 4; ks++)
                ldsm_x4(af[ks][0], af[ks][1], af[ks][2], af[ks][3],
                        sb + SM_A + sw128(abase + ks * 32));
        }
        // B lane addressing (x2 uses lanes 0..15)
        const u32 bbase = (u32)(lane & 7) * 128 + ((lane >> 3) & 1) * 16;

        const int r0 = wrow + (lane >> 2);          // c-frag rows
        const int nlo = (lane & 3) * 2;             // c-frag col offset in tile
        float tb0 = 3.4e38f, tb1 = 3.4e38f;

#pragma unroll 2
        for (int tile = 0; tile < 64; tile++) {
            float c0 = 0.f, c1 = 0.f, c2 = 0.f, c3 = 0.f;
            u32 tb_off = (u32)tile * 8 * 128;
#pragma unroll
            for (int ks = 0; ks < 4; ks++) {
                u32 b0, b1;
                ldsm_x2(b0, b1, sb + SM_B + sw128(tb_off + bbase + ks * 32));
                mma16816(c0, c1, c2, c3,
                         af[ks][0], af[ks][1], af[ks][2], af[ks][3], b0, b1);
            }
            int k0 = tile * 8 + nlo;
            float cn0 = scn[k0], cn1 = scn[k0 + 1];
            float t00 = __fmaf_rn(-2.f, c0, cn0);
            float t01 = __fmaf_rn(-2.f, c1, cn1);
            float t10 = __fmaf_rn(-2.f, c2, cn0);
            float t11 = __fmaf_rn(-2.f, c3, cn1);
            push_cand(scnt, scand, r0,     k0,     t00, tb0);
            push_cand(scnt, scand, r0,     k0 + 1, t01, tb0);
            push_cand(scnt, scand, r0 + 8, k0,     t10, tb1);
            push_cand(scnt, scand, r0 + 8, k0 + 1, t11, tb1);
        }
    }
    __syncthreads();

    // ---- exact rescore + outputs (threads 0..127, one row each) ----
    float sse = 0.f;
    if (tid < M_TILE) {
        const float4* xr = (const float4*)sx + tid * 16;
        const float A = san[tid];
        int nc = scnt[tid];
        float best = 3.4e38f;
        int bi = K_CODES;
        if (nc > MAXC) {                             // overflow: full exact scan
            for (int k = 0; k < K_CODES; k++) {
                float s = exact_score(cb, xr, A, scn[k], k);
                if (s < best) { best = s; bi = k; }
            }
        } else {
            const int* cl = scand + tid * MAXC;
            for (int i = 0; i < nc; i++) {
                int k = cl[i];
                float s = exact_score(cb, xr, A, scn[k], k);
                if (s < best || (s == best && k < bi)) { best = s; bi = k; }
            }
        }

        int vid = blockIdx.x * M_TILE + tid;
        outidx[vid] = (float)bi;
        atomicAdd(&g_hist[bi], 1);

        // quantized_st = x + (q - x); SSE of (q - x)^2.
        // outq is d_out+1 (odd float offset): scalar stores only.
        const float4* qr = (const float4*)(cb + bi * D_DIM);
        float* o = outq + (size_t)vid * D_DIM;
#pragma unroll
        for (int j = 0; j < 16; j++) {
            float4 qv = qr[j], xv = xr[j];
            float d0 = __fadd_rn(qv.x, -xv.x), d1 = __fadd_rn(qv.y, -xv.y);
            float d2 = __fadd_rn(qv.z, -xv.z), d3 = __fadd_rn(qv.w, -xv.w);
            sse += d0 * d0 + d1 * d1 + d2 * d2 + d3 * d3;
            o[4 * j]     = __fadd_rn(xv.x, d0);
            o[4 * j + 1] = __fadd_rn(xv.y, d1);
            o[4 * j + 2] = __fadd_rn(xv.z, d2);
            o[4 * j + 3] = __fadd_rn(xv.w, d3);
        }
    }

    // Block-reduce SSE -> one double atomic per CTA
#pragma unroll
    for (int o = 16; o > 0; o >>= 1)
        sse += __shfl_xor_sync(0xFFFFFFFFu, sse, o);
    if ((tid & 31) == 0) sred[tid >> 5] = (double)sse;
    __syncthreads();
    if (tid == 0) {
        double s = 0.0;
#pragma unroll
        for (int w = 0; w < 8; w++) s += sred[w];
        atomicAdd(&g_sse, s);
    }
}

// ---------------------------------------------------------------------------
// Finalize: loss + perplexity; self-reset accumulators for graph replay.
// ---------------------------------------------------------------------------
__global__ void vq_final(float* __restrict__ out, int nd, int n) {
    int t = threadIdx.x;  // 512
    __shared__ double ssum;
    __shared__ float red[16];

    int h = g_hist[t];
    g_hist[t] = 0;                         // reset for next replay
    if (t == 0) { ssum = g_sse; g_sse = 0.0; }

    float p = (float)h / (float)n;
    float e = p * logf(p + 1e-10f);
#pragma unroll
    for (int o = 16; o > 0; o >>= 1)
        e += __shfl_xor_sync(0xFFFFFFFFu, e, o);
    if ((t & 31) == 0) red[t >> 5] = e;
    __syncthreads();
    if (t < 16) {
        float v = red[t];
#pragma unroll
        for (int o = 8; o > 0; o >>= 1)
            v += __shfl_xor_sync(0xFFFFu, v, o);
        if (t == 0) {
            out[1 + nd] = expf(-v);
            float m = (float)(ssum / (double)nd);
            out[0] = m + 0.25f * m;
        }
    }
}

// ---------------------------------------------------------------------------
extern "C" void kernel_launch(void* const* d_in, const int* in_sizes, int n_in,
                              void* d_out, int out_size) {
    const float* x  = (const float*)d_in[0];
    const float* cb = (const float*)d_in[1];
    float* out = (float*)d_out;

    int nd = in_sizes[0];   // 4194304
    int n  = nd / D_DIM;    // 65536

    cudaFuncSetAttribute(vq_main, cudaFuncAttributeMaxDynamicSharedMemorySize,
                         SMEM_SZ);

    vq_prep<<<64, 256>>>(cb);
    vq_main<<<TILES, TPB, SMEM_SZ>>>(x, cb, out + 1, out + 2 + nd);
    vq_final<<<1, K_CODES>>>(out, nd, n);
}

// round 9
// speedup vs baseline: 2.6251x; 2.6251x over previous
#include <cuda_runtime.h>
#include <cuda_bf16.h>
#include <cstdint>
#include <math.h>

// VectorQuantizer N=65536, D=64, K=512.
// R8: HMMA (mma.sync bf16) screening GEMM + quad-shared row-best margin
// collection (fixes R7's per-lane-best overflow -> global fallback storm)
// + exact fp32 rescore. d_out: [0]=loss, [1..ND]=q_st, [1+ND]=ppl, [2+ND..)=idx.

#define D_DIM   64
#define K_CODES 512
#define M_TILE  128
#define TILES   512          // 65536 / 128
#define TPB     256
#define EPS     5e-3f        // >= 2x two-sided worst-case bf16 screen error
#define MAXC    24

typedef unsigned int u32;

__device__ __nv_bfloat16 g_cbb[K_CODES * D_DIM];  // bf16 codebook
__device__ float  g_cnorm[K_CODES];
__device__ int    g_hist[K_CODES];                // reset by vq_final
__device__ double g_sse;                          // reset by vq_final

__device__ __forceinline__ u32 smem_u32(const void* p) {
    u32 a;
    asm("{ .reg .u64 t; cvta.to.shared.u64 t, %1; cvt.u32.u64 %0, t; }"
        : "=r"(a) : "l"(p));
    return a;
}
__device__ __forceinline__ u32 sw128(u32 b) { return b ^ ((b >> 3) & 0x70); }

__device__ __forceinline__ void ldsm_x4(u32& r0, u32& r1, u32& r2, u32& r3, u32 a) {
    asm volatile("ldmatrix.sync.aligned.m8n8.x4.shared.b16 {%0,%1,%2,%3}, [%4];"
                 : "=r"(r0), "=r"(r1), "=r"(r2), "=r"(r3) : "r"(a));
}
__device__ __forceinline__ void ldsm_x2(u32& r0, u32& r1, u32 a) {
    asm volatile("ldmatrix.sync.aligned.m8n8.x2.shared.b16 {%0,%1}, [%2];"
                 : "=r"(r0), "=r"(r1) : "r"(a));
}
__device__ __forceinline__ void mma16816(float& c0, float& c1, float& c2, float& c3,
                                         u32 a0, u32 a1, u32 a2, u32 a3,
                                         u32 b0, u32 b1) {
    asm volatile(
        "mma.sync.aligned.m16n8k16.row.col.f32.bf16.bf16.f32 "
        "{%0,%1,%2,%3}, {%4,%5,%6,%7}, {%8,%9}, {%0,%1,%2,%3};"
        : "+f"(c0), "+f"(c1), "+f"(c2), "+f"(c3)
        : "r"(a0), "r"(a1), "r"(a2), "r"(a3), "r"(b0), "r"(b1));
}

// ---- smem layout (bytes) ----
#define SM_X    0                        // 128*64 f32 = 32768
#define SM_A    32768                    // 128 rows * 128B bf16 (SW128) = 16384
#define SM_B    49152                    // 512 rows * 128B bf16 (SW128) = 65536
#define SM_CN   114688                   // 512 f32 = 2048
#define SM_AN   116736                   // 128 f32 = 512
#define SM_CNT  117248                   // 128 int = 512
#define SM_CAND 117760                   // 128*24 int = 12288
#define SM_RED  130048                   // 8 double = 64
#define SMEM_SZ 130112

// ---------------------------------------------------------------------------
// Prep: bf16 codebook + fp32 norms (warp per code, coalesced).
// ---------------------------------------------------------------------------
__global__ void vq_prep(const float* __restrict__ cb) {
    int gt = blockIdx.x * 256 + threadIdx.x;
    int w = gt >> 5, lane = gt & 31;                 // w = code 0..511
    const float* c = cb + w * D_DIM;
    float v0 = c[lane], v1 = c[lane + 32];
    g_cbb[w * D_DIM + lane]      = __float2bfloat16(v0);
    g_cbb[w * D_DIM + lane + 32] = __float2bfloat16(v1);
    double s = (double)__fmul_rn(v0, v0) + (double)__fmul_rn(v1, v1);
#pragma unroll
    for (int o = 16; o > 0; o >>= 1)
        s += __shfl_xor_sync(0xFFFFFFFFu, s, o);
    if (lane == 0) g_cnorm[w] = (float)s;
}

// Exact fp32 score s = fl( fl(A - 2*dot) + C ), 4-chain fp32 dot
__device__ __forceinline__ float exact_score(const float* __restrict__ cb,
                                             const float4* __restrict__ xr,
                                             float A, float C, int k) {
    const float4* cr = (const float4*)(cb + k * D_DIM);
    float a0 = 0.f, a1 = 0.f, a2 = 0.f, a3 = 0.f;
#pragma unroll
    for (int j = 0; j < D_DIM / 4; j++) {
        float4 cv = cr[j], xv = xr[j];
        a0 = __fmaf_rn(xv.x, cv.x, a0);
        a1 = __fmaf_rn(xv.y, cv.y, a1);
        a2 = __fmaf_rn(xv.z, cv.z, a2);
        a3 = __fmaf_rn(xv.w, cv.w, a3);
    }
    float dot = (a0 + a1) + (a2 + a3);
    return __fadd_rn(__fmaf_rn(-2.f, dot, A), C);
}

// ---------------------------------------------------------------------------
// Main: one CTA per 128-row tile. Screen via HMMA, rescore exactly.
// ---------------------------------------------------------------------------
__global__ __launch_bounds__(TPB, 1)
void vq_main(const float* __restrict__ x, const float* __restrict__ cb,
             float* __restrict__ outq, float* __restrict__ outidx) {
    extern __shared__ char smem[];
    const u32 sb  = smem_u32(smem);
    const int tid = threadIdx.x;
    const int lane = tid & 31;
    const int wrow = (tid >> 5) * 16;               // warp's first local row

    float* sx   = (float*)(smem + SM_X);
    float* scn  = (float*)(smem + SM_CN);
    float* san  = (float*)(smem + SM_AN);
    int*   scnt = (int*)(smem + SM_CNT);
    int*   scand= (int*)(smem + SM_CAND);
    double* sred= (double*)(smem + SM_RED);

    // x tile -> smem (coalesced float4)
    {
        const float4* xs = (const float4*)(x + (size_t)blockIdx.x * M_TILE * D_DIM);
        float4* xd = (float4*)sx;
#pragma unroll
        for (int i = 0; i < 8; i++) xd[tid + 256 * i] = xs[tid + 256 * i];
    }
    // B: bf16 codebook -> smem SW128 (2 rows/thread, 8x uint4 each)
    {
#pragma unroll
        for (int rr = 0; rr < 2; rr++) {
            int row = tid * 2 + rr;
            const uint4* src = (const uint4*)(g_cbb + row * D_DIM);
#pragma unroll
            for (int j = 0; j < 8; j++)
                *(uint4*)(smem + SM_B + sw128(row * 128 + j * 16)) = src[j];
        }
    }
    scn[tid]       = g_cnorm[tid];
    scn[tid + 256] = g_cnorm[tid + 256];
    if (tid < M_TILE) scnt[tid] = 0;
    __syncthreads();

    // A: convert x rows to bf16 SW128 + exact fp32 row norm (threads 0..127)
    if (tid < M_TILE) {
        const float4* xr = (const float4*)sx + tid * 16;
        double sa = 0.0;
#pragma unroll
        for (int j = 0; j < 16; j++) {
            float4 v = xr[j];
            sa += (double)__fmul_rn(v.x, v.x); sa += (double)__fmul_rn(v.y, v.y);
            sa += (double)__fmul_rn(v.z, v.z); sa += (double)__fmul_rn(v.w, v.w);
            __nv_bfloat162 p0 = __floats2bfloat162_rn(v.x, v.y);
            __nv_bfloat162 p1 = __floats2bfloat162_rn(v.z, v.w);
            u32 base = tid * 128 + j * 8;
            *(u32*)(smem + SM_A + sw128(base))     = *(u32*)&p0;
            *(u32*)(smem + SM_A + sw128(base + 4)) = *(u32*)&p1;
        }
        san[tid] = (float)sa;
    }
    __syncthreads();

    // ---- screening GEMM: each warp does rows [wrow, wrow+16) x 512 codes ----
    {
        // A fragments: 4 k-steps, resident (16 regs)
        u32 af[4][4];
        {
            int r    = (lane & 7) + ((lane & 8) ? 8 : 0);
            int half = (lane >> 4) & 1;
            u32 abase = (u32)(wrow + r) * 128 + half * 16;
#pragma unroll
            for (int ks = 0; ks < 4; ks++)
                ldsm_x4(af[ks][0], af[ks][1], af[ks][2], af[ks][3],
                        sb + SM_A + sw128(abase + ks * 32));
        }
        // B lane addressing (x2 uses lanes 0..15)
        const u32 bbase = (u32)(lane & 7) * 128 + ((lane >> 3) & 1) * 16;

        const int r0 = wrow + (lane >> 2);          // c-frag rows
        const int nlo = (lane & 3) * 2;             // c-frag col offset in tile
        // Quad-shared running row bests (lanes 4j..4j+3 hold identical values)
        float tb0 = 3.4e38f, tb1 = 3.4e38f;

#pragma unroll 2
        for (int tile = 0; tile < 64; tile++) {
            float c0 = 0.f, c1 = 0.f, c2 = 0.f, c3 = 0.f;
            u32 tb_off = (u32)tile * 8 * 128;
#pragma unroll
            for (int ks = 0; ks < 4; ks++) {
                u32 b0, b1;
                ldsm_x2(b0, b1, sb + SM_B + sw128(tb_off + bbase + ks * 32));
                mma16816(c0, c1, c2, c3,
                         af[ks][0], af[ks][1], af[ks][2], af[ks][3], b0, b1);
            }
            int k0 = tile * 8 + nlo;
            float cn0 = scn[k0], cn1 = scn[k0 + 1];
            float t00 = __fmaf_rn(-2.f, c0, cn0);
            float t01 = __fmaf_rn(-2.f, c1, cn1);
            float t10 = __fmaf_rn(-2.f, c2, cn0);
            float t11 = __fmaf_rn(-2.f, c3, cn1);

            // Quad-reduce this tile's row minimum; all 4 lanes get same value.
            float m0 = fminf(t00, t01);
            m0 = fminf(m0, __shfl_xor_sync(0xFFFFFFFFu, m0, 1));
            m0 = fminf(m0, __shfl_xor_sync(0xFFFFFFFFu, m0, 2));
            tb0 = fminf(tb0, m0);
            float m1 = fminf(t10, t11);
            m1 = fminf(m1, __shfl_xor_sync(0xFFFFFFFFu, m1, 1));
            m1 = fminf(m1, __shfl_xor_sync(0xFFFFFFFFu, m1, 2));
            tb1 = fminf(tb1, m1);

            // Margin pushes against the SHARED row best (few per row total).
            if (t00 < tb0 + EPS) {
                int p = atomicAdd(&scnt[r0], 1);
                if (p < MAXC) scand[r0 * MAXC + p] = k0;
            }
            if (t01 < tb0 + EPS) {
                int p = atomicAdd(&scnt[r0], 1);
                if (p < MAXC) scand[r0 * MAXC + p] = k0 + 1;
            }
            if (t10 < tb1 + EPS) {
                int p = atomicAdd(&scnt[r0 + 8], 1);
                if (p < MAXC) scand[(r0 + 8) * MAXC + p] = k0;
            }
            if (t11 < tb1 + EPS) {
                int p = atomicAdd(&scnt[r0 + 8], 1);
                if (p < MAXC) scand[(r0 + 8) * MAXC + p] = k0 + 1;
            }
        }
    }
    __syncthreads();

    // ---- exact rescore + outputs (threads 0..127, one row each) ----
    float sse = 0.f;
    if (tid < M_TILE) {
        const float4* xr = (const float4*)sx + tid * 16;
        const float A = san[tid];
        int nc = scnt[tid];
        float best = 3.4e38f;
        int bi = K_CODES;
        if (nc > MAXC) {                             // overflow: full exact scan
            for (int k = 0; k < K_CODES; k++) {
                float s = exact_score(cb, xr, A, scn[k], k);
                if (s < best) { best = s; bi = k; }
            }
        } else {
            const int* cl = scand + tid * MAXC;
            for (int i = 0; i < nc; i++) {
                int k = cl[i];
                float s = exact_score(cb, xr, A, scn[k], k);
                if (s < best || (s == best && k < bi)) { best = s; bi = k; }
            }
        }

        int vid = blockIdx.x * M_TILE + tid;
        outidx[vid] = (float)bi;
        atomicAdd(&g_hist[bi], 1);

        // quantized_st = x + (q - x); SSE of (q - x)^2.
        // outq is d_out+1 (odd float offset): scalar stores only.
        const float4* qr = (const float4*)(cb + bi * D_DIM);
        float* o = outq + (size_t)vid * D_DIM;
#pragma unroll
        for (int j = 0; j < 16; j++) {
            float4 qv = qr[j], xv = xr[j];
            float d0 = __fadd_rn(qv.x, -xv.x), d1 = __fadd_rn(qv.y, -xv.y);
            float d2 = __fadd_rn(qv.z, -xv.z), d3 = __fadd_rn(qv.w, -xv.w);
            sse += d0 * d0 + d1 * d1 + d2 * d2 + d3 * d3;
            o[4 * j]     = __fadd_rn(xv.x, d0);
            o[4 * j + 1] = __fadd_rn(xv.y, d1);
            o[4 * j + 2] = __fadd_rn(xv.z, d2);
            o[4 * j + 3] = __fadd_rn(xv.w, d3);
        }
    }

    // Block-reduce SSE -> one double atomic per CTA
#pragma unroll
    for (int o = 16; o > 0; o >>= 1)
        sse += __shfl_xor_sync(0xFFFFFFFFu, sse, o);
    if ((tid & 31) == 0) sred[tid >> 5] = (double)sse;
    __syncthreads();
    if (tid == 0) {
        double s = 0.0;
#pragma unroll
        for (int w = 0; w < 8; w++) s += sred[w];
        atomicAdd(&g_sse, s);
    }
}

// ---------------------------------------------------------------------------
// Finalize: loss + perplexity; self-reset accumulators for graph replay.
// ---------------------------------------------------------------------------
__global__ void vq_final(float* __restrict__ out, int nd, int n) {
    int t = threadIdx.x;  // 512
    __shared__ double ssum;
    __shared__ float red[16];

    int h = g_hist[t];
    g_hist[t] = 0;                         // reset for next replay
    if (t == 0) { ssum = g_sse; g_sse = 0.0; }

    float p = (float)h / (float)n;
    float e = p * logf(p + 1e-10f);
#pragma unroll
    for (int o = 16; o > 0; o >>= 1)
        e += __shfl_xor_sync(0xFFFFFFFFu, e, o);
    if ((t & 31) == 0) red[t >> 5] = e;
    __syncthreads();
    if (t < 16) {
        float v = red[t];
#pragma unroll
        for (int o = 8; o > 0; o >>= 1)
            v += __shfl_xor_sync(0xFFFFu, v, o);
        if (t == 0) {
            out[1 + nd] = expf(-v);
            float m = (float)(ssum / (double)nd);
            out[0] = m + 0.25f * m;
        }
    }
}

// ---------------------------------------------------------------------------
extern "C" void kernel_launch(void* const* d_in, const int* in_sizes, int n_in,
                              void* d_out, int out_size) {
    const float* x  = (const float*)d_in[0];
    const float* cb = (const float*)d_in[1];
    float* out = (float*)d_out;

    int nd = in_sizes[0];   // 4194304
    int n  = nd / D_DIM;    // 65536

    cudaFuncSetAttribute(vq_main, cudaFuncAttributeMaxDynamicSharedMemorySize,
                         SMEM_SZ);

    vq_prep<<<64, 256>>>(cb);
    vq_main<<<TILES, TPB, SMEM_SZ>>>(x, cb, out + 1, out + 2 + nd);
    vq_final<<<1, K_CODES>>>(out, nd, n);
}

// round 10
// speedup vs baseline: 4.9000x; 1.8666x over previous
#include <cuda_runtime.h>
#include <cuda_bf16.h>
#include <cstdint>
#include <math.h>

// VectorQuantizer N=65536, D=64, K=512.
// R10: two-phase HMMA screen (phase 1 = exact row screen-min, phase 2 = push
// candidates vs fixed rowmin+EPS threshold) + exact fp32 rescore.
// Fixes R8/R9's running-best push inflation -> overflow fallback storms.
// d_out: [0]=loss, [1..ND]=q_st, [1+ND]=ppl, [2+ND..)=idx.

#define D_DIM   64
#define K_CODES 512
#define M_TILE  128
#define TILES   512          // 65536 / 128
#define TPB     256
#define EPS     5e-3f        // >= 2x two-sided worst-case bf16 screen error
#define MAXC    24

typedef unsigned int u32;

__device__ __nv_bfloat16 g_cbb[K_CODES * D_DIM];  // bf16 codebook
__device__ float  g_cnorm[K_CODES];
__device__ int    g_hist[K_CODES];                // reset by vq_final
__device__ double g_sse;                          // reset by vq_final

__device__ __forceinline__ u32 smem_u32(const void* p) {
    u32 a;
    asm("{ .reg .u64 t; cvta.to.shared.u64 t, %1; cvt.u32.u64 %0, t; }"
        : "=r"(a) : "l"(p));
    return a;
}
__device__ __forceinline__ u32 sw128(u32 b) { return b ^ ((b >> 3) & 0x70); }

__device__ __forceinline__ void ldsm_x4(u32& r0, u32& r1, u32& r2, u32& r3, u32 a) {
    asm volatile("ldmatrix.sync.aligned.m8n8.x4.shared.b16 {%0,%1,%2,%3}, [%4];"
                 : "=r"(r0), "=r"(r1), "=r"(r2), "=r"(r3) : "r"(a));
}
__device__ __forceinline__ void ldsm_x2(u32& r0, u32& r1, u32 a) {
    asm volatile("ldmatrix.sync.aligned.m8n8.x2.shared.b16 {%0,%1}, [%2];"
                 : "=r"(r0), "=r"(r1) : "r"(a));
}
__device__ __forceinline__ void mma16816(float& c0, float& c1, float& c2, float& c3,
                                         u32 a0, u32 a1, u32 a2, u32 a3,
                                         u32 b0, u32 b1) {
    asm volatile(
        "mma.sync.aligned.m16n8k16.row.col.f32.bf16.bf16.f32 "
        "{%0,%1,%2,%3}, {%4,%5,%6,%7}, {%8,%9}, {%0,%1,%2,%3};"
        : "+f"(c0), "+f"(c1), "+f"(c2), "+f"(c3)
        : "r"(a0), "r"(a1), "r"(a2), "r"(a3), "r"(b0), "r"(b1));
}

// ---- smem layout (bytes) ----
#define SM_X    0                        // 128*64 f32 = 32768
#define SM_A    32768                    // 128 rows * 128B bf16 (SW128) = 16384
#define SM_B    49152                    // 512 rows * 128B bf16 (SW128) = 65536
#define SM_CN   114688                   // 512 f32 = 2048
#define SM_AN   116736                   // 128 f32 = 512
#define SM_CNT  117248                   // 128 int = 512
#define SM_CAND 117760                   // 128*24 int = 12288
#define SM_RED  130048                   // 8 double = 64
#define SMEM_SZ 130112

// ---------------------------------------------------------------------------
// Prep: bf16 codebook + fp32 norms (warp per code, coalesced).
// ---------------------------------------------------------------------------
__global__ void vq_prep(const float* __restrict__ cb) {
    int gt = blockIdx.x * 256 + threadIdx.x;
    int w = gt >> 5, lane = gt & 31;                 // w = code 0..511
    const float* c = cb + w * D_DIM;
    float v0 = c[lane], v1 = c[lane + 32];
    g_cbb[w * D_DIM + lane]      = __float2bfloat16(v0);
    g_cbb[w * D_DIM + lane + 32] = __float2bfloat16(v1);
    double s = (double)__fmul_rn(v0, v0) + (double)__fmul_rn(v1, v1);
#pragma unroll
    for (int o = 16; o > 0; o >>= 1)
        s += __shfl_xor_sync(0xFFFFFFFFu, s, o);
    if (lane == 0) g_cnorm[w] = (float)s;
}

// Exact fp32 score s = fl( fl(A - 2*dot) + C ), 4-chain fp32 dot
__device__ __forceinline__ float exact_score(const float* __restrict__ cb,
                                             const float4* __restrict__ xr,
                                             float A, float C, int k) {
    const float4* cr = (const float4*)(cb + k * D_DIM);
    float a0 = 0.f, a1 = 0.f, a2 = 0.f, a3 = 0.f;
#pragma unroll
    for (int j = 0; j < D_DIM / 4; j++) {
        float4 cv = cr[j], xv = xr[j];
        a0 = __fmaf_rn(xv.x, cv.x, a0);
        a1 = __fmaf_rn(xv.y, cv.y, a1);
        a2 = __fmaf_rn(xv.z, cv.z, a2);
        a3 = __fmaf_rn(xv.w, cv.w, a3);
    }
    float dot = (a0 + a1) + (a2 + a3);
    return __fadd_rn(__fmaf_rn(-2.f, dot, A), C);
}

// ---------------------------------------------------------------------------
// Main: one CTA per 128-row tile. Two-phase HMMA screen, exact rescore.
// ---------------------------------------------------------------------------
__global__ __launch_bounds__(TPB, 1)
void vq_main(const float* __restrict__ x, const float* __restrict__ cb,
             float* __restrict__ outq, float* __restrict__ outidx) {
    extern __shared__ char smem[];
    const u32 sb  = smem_u32(smem);
    const int tid = threadIdx.x;
    const int lane = tid & 31;
    const int wrow = (tid >> 5) * 16;               // warp's first local row

    float* sx   = (float*)(smem + SM_X);
    float* scn  = (float*)(smem + SM_CN);
    float* san  = (float*)(smem + SM_AN);
    int*   scnt = (int*)(smem + SM_CNT);
    int*   scand= (int*)(smem + SM_CAND);
    double* sred= (double*)(smem + SM_RED);

    // x tile -> smem (coalesced float4)
    {
        const float4* xs = (const float4*)(x + (size_t)blockIdx.x * M_TILE * D_DIM);
        float4* xd = (float4*)sx;
#pragma unroll
        for (int i = 0; i < 8; i++) xd[tid + 256 * i] = xs[tid + 256 * i];
    }
    // B: bf16 codebook -> smem SW128 (2 rows/thread, 8x uint4 each)
    {
#pragma unroll
        for (int rr = 0; rr < 2; rr++) {
            int row = tid * 2 + rr;
            const uint4* src = (const uint4*)(g_cbb + row * D_DIM);
#pragma unroll
            for (int j = 0; j < 8; j++)
                *(uint4*)(smem + SM_B + sw128(row * 128 + j * 16)) = src[j];
        }
    }
    scn[tid]       = g_cnorm[tid];
    scn[tid + 256] = g_cnorm[tid + 256];
    if (tid < M_TILE) scnt[tid] = 0;
    __syncthreads();

    // A: convert x rows to bf16 SW128 + exact fp32 row norm (threads 0..127)
    if (tid < M_TILE) {
        const float4* xr = (const float4*)sx + tid * 16;
        double sa = 0.0;
#pragma unroll
        for (int j = 0; j < 16; j++) {
            float4 v = xr[j];
            sa += (double)__fmul_rn(v.x, v.x); sa += (double)__fmul_rn(v.y, v.y);
            sa += (double)__fmul_rn(v.z, v.z); sa += (double)__fmul_rn(v.w, v.w);
            __nv_bfloat162 p0 = __floats2bfloat162_rn(v.x, v.y);
            __nv_bfloat162 p1 = __floats2bfloat162_rn(v.z, v.w);
            u32 base = tid * 128 + j * 8;
            *(u32*)(smem + SM_A + sw128(base))     = *(u32*)&p0;
            *(u32*)(smem + SM_A + sw128(base + 4)) = *(u32*)&p1;
        }
        san[tid] = (float)sa;
    }
    __syncthreads();

    // ---- screening: each warp handles rows [wrow, wrow+16) x 512 codes ----
    {
        // A fragments: 4 k-steps, resident (16 regs)
        u32 af[4][4];
        {
            int r    = (lane & 7) + ((lane & 8) ? 8 : 0);
            int half = (lane >> 4) & 1;
            u32 abase = (u32)(wrow + r) * 128 + half * 16;
#pragma unroll
            for (int ks = 0; ks < 4; ks++)
                ldsm_x4(af[ks][0], af[ks][1], af[ks][2], af[ks][3],
                        sb + SM_A + sw128(abase + ks * 32));
        }
        const u32 bbase = (u32)(lane & 7) * 128 + ((lane >> 3) & 1) * 16;
        const int r0 = wrow + (lane >> 2);          // c-frag rows
        const int nlo = (lane & 3) * 2;             // c-frag col offset in tile

        // ---- Phase 1: true row screen minima (no shfl inside the loop) ----
        float tb0 = 3.4e38f, tb1 = 3.4e38f;
#pragma unroll 4
        for (int tile = 0; tile < 64; tile++) {
            float c0 = 0.f, c1 = 0.f, c2 = 0.f, c3 = 0.f;
            u32 tb_off = (u32)tile * 8 * 128;
#pragma unroll
            for (int ks = 0; ks < 4; ks++) {
                u32 b0, b1;
                ldsm_x2(b0, b1, sb + SM_B + sw128(tb_off + bbase + ks * 32));
                mma16816(c0, c1, c2, c3,
                         af[ks][0], af[ks][1], af[ks][2], af[ks][3], b0, b1);
            }
            int k0 = tile * 8 + nlo;
            float cn0 = scn[k0], cn1 = scn[k0 + 1];
            tb0 = fminf(tb0, fminf(__fmaf_rn(-2.f, c0, cn0),
                                   __fmaf_rn(-2.f, c1, cn1)));
            tb1 = fminf(tb1, fminf(__fmaf_rn(-2.f, c2, cn0),
                                   __fmaf_rn(-2.f, c3, cn1)));
        }
        // One quad-reduce at the end: full row minima
        tb0 = fminf(tb0, __shfl_xor_sync(0xFFFFFFFFu, tb0, 1));
        tb0 = fminf(tb0, __shfl_xor_sync(0xFFFFFFFFu, tb0, 2));
        tb1 = fminf(tb1, __shfl_xor_sync(0xFFFFFFFFu, tb1, 1));
        tb1 = fminf(tb1, __shfl_xor_sync(0xFFFFFFFFu, tb1, 2));
        const float thr0 = tb0 + EPS, thr1 = tb1 + EPS;

        // ---- Phase 2: recompute, push candidates vs fixed thresholds ----
#pragma unroll 4
        for (int tile = 0; tile < 64; tile++) {
            float c0 = 0.f, c1 = 0.f, c2 = 0.f, c3 = 0.f;
            u32 tb_off = (u32)tile * 8 * 128;
#pragma unroll
            for (int ks = 0; ks < 4; ks++) {
                u32 b0, b1;
                ldsm_x2(b0, b1, sb + SM_B + sw128(tb_off + bbase + ks * 32));
                mma16816(c0, c1, c2, c3,
                         af[ks][0], af[ks][1], af[ks][2], af[ks][3], b0, b1);
            }
            int k0 = tile * 8 + nlo;
            float cn0 = scn[k0], cn1 = scn[k0 + 1];
            float t00 = __fmaf_rn(-2.f, c0, cn0);
            float t01 = __fmaf_rn(-2.f, c1, cn1);
            float t10 = __fmaf_rn(-2.f, c2, cn0);
            float t11 = __fmaf_rn(-2.f, c3, cn1);
            if (t00 < thr0) {
                int p = atomicAdd(&scnt[r0], 1);
                if (p < MAXC) scand[r0 * MAXC + p] = k0;
            }
            if (t01 < thr0) {
                int p = atomicAdd(&scnt[r0], 1);
                if (p < MAXC) scand[r0 * MAXC + p] = k0 + 1;
            }
            if (t10 < thr1) {
                int p = atomicAdd(&scnt[r0 + 8], 1);
                if (p < MAXC) scand[(r0 + 8) * MAXC + p] = k0;
            }
            if (t11 < thr1) {
                int p = atomicAdd(&scnt[r0 + 8], 1);
                if (p < MAXC) scand[(r0 + 8) * MAXC + p] = k0 + 1;
            }
        }
    }
    __syncthreads();

    // ---- exact rescore + outputs (threads 0..127, one row each) ----
    float sse = 0.f;
    if (tid < M_TILE) {
        const float4* xr = (const float4*)sx + tid * 16;
        const float A = san[tid];
        int nc = scnt[tid];
        float best = 3.4e38f;
        int bi = K_CODES;
        if (nc > MAXC) {                             // overflow: full exact scan
            for (int k = 0; k < K_CODES; k++) {
                float s = exact_score(cb, xr, A, scn[k], k);
                if (s < best) { best = s; bi = k; }
            }
        } else {
            const int* cl = scand + tid * MAXC;
            for (int i = 0; i < nc; i++) {
                int k = cl[i];
                float s = exact_score(cb, xr, A, scn[k], k);
                if (s < best || (s == best && k < bi)) { best = s; bi = k; }
            }
        }

        int vid = blockIdx.x * M_TILE + tid;
        outidx[vid] = (float)bi;
        atomicAdd(&g_hist[bi], 1);

        // quantized_st = x + (q - x); SSE of (q - x)^2.
        // outq is d_out+1 (odd float offset): scalar stores only.
        const float4* qr = (const float4*)(cb + bi * D_DIM);
        float* o = outq + (size_t)vid * D_DIM;
#pragma unroll
        for (int j = 0; j < 16; j++) {
            float4 qv = qr[j], xv = xr[j];
            float d0 = __fadd_rn(qv.x, -xv.x), d1 = __fadd_rn(qv.y, -xv.y);
            float d2 = __fadd_rn(qv.z, -xv.z), d3 = __fadd_rn(qv.w, -xv.w);
            sse += d0 * d0 + d1 * d1 + d2 * d2 + d3 * d3;
            o[4 * j]     = __fadd_rn(xv.x, d0);
            o[4 * j + 1] = __fadd_rn(xv.y, d1);
            o[4 * j + 2] = __fadd_rn(xv.z, d2);
            o[4 * j + 3] = __fadd_rn(xv.w, d3);
        }
    }

    // Block-reduce SSE -> one double atomic per CTA
#pragma unroll
    for (int o = 16; o > 0; o >>= 1)
        sse += __shfl_xor_sync(0xFFFFFFFFu, sse, o);
    if ((tid & 31) == 0) sred[tid >> 5] = (double)sse;
    __syncthreads();
    if (tid == 0) {
        double s = 0.0;
#pragma unroll
        for (int w = 0; w < 8; w++) s += sred[w];
        atomicAdd(&g_sse, s);
    }
}

// ---------------------------------------------------------------------------
// Finalize: loss + perplexity; self-reset accumulators for graph replay.
// ---------------------------------------------------------------------------
__global__ void vq_final(float* __restrict__ out, int nd, int n) {
    int t = threadIdx.x;  // 512
    __shared__ double ssum;
    __shared__ float red[16];

    int h = g_hist[t];
    g_hist[t] = 0;                         // reset for next replay
    if (t == 0) { ssum = g_sse; g_sse = 0.0; }

    float p = (float)h / (float)n;
    float e = p * logf(p + 1e-10f);
#pragma unroll
    for (int o = 16; o > 0; o >>= 1)
        e += __shfl_xor_sync(0xFFFFFFFFu, e, o);
    if ((t & 31) == 0) red[t >> 5] = e;
    __syncthreads();
    if (t < 16) {
        float v = red[t];
#pragma unroll
        for (int o = 8; o > 0; o >>= 1)
            v += __shfl_xor_sync(0xFFFFu, v, o);
        if (t == 0) {
            out[1 + nd] = expf(-v);
            float m = (float)(ssum / (double)nd);
            out[0] = m + 0.25f * m;
        }
    }
}

// ---------------------------------------------------------------------------
extern "C" void kernel_launch(void* const* d_in, const int* in_sizes, int n_in,
                              void* d_out, int out_size) {
    const float* x  = (const float*)d_in[0];
    const float* cb = (const float*)d_in[1];
    float* out = (float*)d_out;

    int nd = in_sizes[0];   // 4194304
    int n  = nd / D_DIM;    // 65536

    cudaFuncSetAttribute(vq_main, cudaFuncAttributeMaxDynamicSharedMemorySize,
                         SMEM_SZ);

    vq_prep<<<64, 256>>>(cb);
    vq_main<<<TILES, TPB, SMEM_SZ>>>(x, cb, out + 1, out + 2 + nd);
    vq_final<<<1, K_CODES>>>(out, nd, n);
}

// round 11
// speedup vs baseline: 5.9274x; 1.2097x over previous
#include <cuda_runtime.h>
#include <cuda_bf16.h>
#include <cstdint>
#include <math.h>

// VectorQuantizer N=65536, D=64, K=512.
// R11: two-phase HMMA screen + exact rescore, now at 2 CTAs/SM (no fp32 x
// mirror in smem) with all 256 threads active in convert/rescore/epilogue
// (2 threads per row, u64-key atomicMin argmin merge).
// d_out: [0]=loss, [1..ND]=q_st, [1+ND]=ppl, [2+ND..)=idx.

#define D_DIM   64
#define K_CODES 512
#define M_TILE  128
#define TILES   512          // 65536 / 128
#define TPB     256
#define EPS     5e-3f        // >= 2x two-sided worst-case bf16 screen error
#define MAXC    24

typedef unsigned int u32;
typedef unsigned long long u64;

__device__ __nv_bfloat16 g_cbb[K_CODES * D_DIM];  // bf16 codebook
__device__ float  g_cnorm[K_CODES];
__device__ int    g_hist[K_CODES];                // reset by vq_final
__device__ double g_sse;                          // reset by vq_final

__device__ __forceinline__ u32 smem_u32(const void* p) {
    u32 a;
    asm("{ .reg .u64 t; cvta.to.shared.u64 t, %1; cvt.u32.u64 %0, t; }"
        : "=r"(a) : "l"(p));
    return a;
}
__device__ __forceinline__ u32 sw128(u32 b) { return b ^ ((b >> 3) & 0x70); }

__device__ __forceinline__ void ldsm_x4(u32& r0, u32& r1, u32& r2, u32& r3, u32 a) {
    asm volatile("ldmatrix.sync.aligned.m8n8.x4.shared.b16 {%0,%1,%2,%3}, [%4];"
                 : "=r"(r0), "=r"(r1), "=r"(r2), "=r"(r3) : "r"(a));
}
__device__ __forceinline__ void ldsm_x2(u32& r0, u32& r1, u32 a) {
    asm volatile("ldmatrix.sync.aligned.m8n8.x2.shared.b16 {%0,%1}, [%2];"
                 : "=r"(r0), "=r"(r1) : "r"(a));
}
__device__ __forceinline__ void mma16816(float& c0, float& c1, float& c2, float& c3,
                                         u32 a0, u32 a1, u32 a2, u32 a3,
                                         u32 b0, u32 b1) {
    asm volatile(
        "mma.sync.aligned.m16n8k16.row.col.f32.bf16.bf16.f32 "
        "{%0,%1,%2,%3}, {%4,%5,%6,%7}, {%8,%9}, {%0,%1,%2,%3};"
        : "+f"(c0), "+f"(c1), "+f"(c2), "+f"(c3)
        : "r"(a0), "r"(a1), "r"(a2), "r"(a3), "r"(b0), "r"(b1));
}

// ---- smem layout (bytes), total ~98 KB -> 2 CTAs/SM ----
#define SM_A    0                        // 128 rows * 128B bf16 (SW128) = 16384
#define SM_B    16384                    // 512 rows * 128B bf16 (SW128) = 65536
#define SM_CN   81920                    // 512 f32 = 2048
#define SM_AN   83968                    // 128 f32 = 512
#define SM_AND  84480                    // 256 double (half norms) = 2048
#define SM_CNT  86528                    // 128 int = 512
#define SM_CAND 87040                    // 128*24 int = 12288
#define SM_KEY  99328                    // 128 u64 = 1024
#define SM_RED  100352                   // 8 double = 64
#define SMEM_SZ 100416

// ---------------------------------------------------------------------------
// Prep: bf16 codebook + fp32 norms (warp per code, coalesced).
// ---------------------------------------------------------------------------
__global__ void vq_prep(const float* __restrict__ cb) {
    int gt = blockIdx.x * 256 + threadIdx.x;
    int w = gt >> 5, lane = gt & 31;                 // w = code 0..511
    const float* c = cb + w * D_DIM;
    float v0 = c[lane], v1 = c[lane + 32];
    g_cbb[w * D_DIM + lane]      = __float2bfloat16(v0);
    g_cbb[w * D_DIM + lane + 32] = __float2bfloat16(v1);
    double s = (double)__fmul_rn(v0, v0) + (double)__fmul_rn(v1, v1);
#pragma unroll
    for (int o = 16; o > 0; o >>= 1)
        s += __shfl_xor_sync(0xFFFFFFFFu, s, o);
    if (lane == 0) g_cnorm[w] = (float)s;
}

// Exact fp32 score s = fl( fl(A - 2*dot) + C ), 4-chain fp32 dot.
// x row and cb row read from global (L1/L2 hot).
__device__ __forceinline__ float exact_score(const float* __restrict__ cb,
                                             const float4* __restrict__ xr,
                                             float A, float C, int k) {
    const float4* cr = (const float4*)(cb + k * D_DIM);
    float a0 = 0.f, a1 = 0.f, a2 = 0.f, a3 = 0.f;
#pragma unroll
    for (int j = 0; j < D_DIM / 4; j++) {
        float4 cv = cr[j], xv = xr[j];
        a0 = __fmaf_rn(xv.x, cv.x, a0);
        a1 = __fmaf_rn(xv.y, cv.y, a1);
        a2 = __fmaf_rn(xv.z, cv.z, a2);
        a3 = __fmaf_rn(xv.w, cv.w, a3);
    }
    float dot = (a0 + a1) + (a2 + a3);
    return __fadd_rn(__fmaf_rn(-2.f, dot, A), C);
}

// ---------------------------------------------------------------------------
// Main: one CTA per 128-row tile. Two-phase HMMA screen, exact rescore.
// ---------------------------------------------------------------------------
__global__ __launch_bounds__(TPB, 2)
void vq_main(const float* __restrict__ x, const float* __restrict__ cb,
             float* __restrict__ outq, float* __restrict__ outidx) {
    extern __shared__ char smem[];
    const u32 sb  = smem_u32(smem);
    const int tid = threadIdx.x;
    const int lane = tid & 31;
    const int wrow = (tid >> 5) * 16;               // warp's first local row
    const int row  = tid & 127;                     // pair row
    const int half = tid >> 7;                      // 0: cols 0-31, 1: cols 32-63

    float*  scn  = (float*)(smem + SM_CN);
    float*  san  = (float*)(smem + SM_AN);
    double* sand = (double*)(smem + SM_AND);
    int*    scnt = (int*)(smem + SM_CNT);
    int*    scand= (int*)(smem + SM_CAND);
    u64*    skey = (u64*)(smem + SM_KEY);
    double* sred = (double*)(smem + SM_RED);

    // B: bf16 codebook -> smem SW128 (2 rows/thread, 8x uint4 each)
    {
#pragma unroll
        for (int rr = 0; rr < 2; rr++) {
            int r = tid * 2 + rr;
            const uint4* src = (const uint4*)(g_cbb + r * D_DIM);
#pragma unroll
            for (int j = 0; j < 8; j++)
                *(uint4*)(smem + SM_B + sw128(r * 128 + j * 16)) = src[j];
        }
    }
    scn[tid]       = g_cnorm[tid];
    scn[tid + 256] = g_cnorm[tid + 256];
    if (tid < M_TILE) { scnt[tid] = 0; skey[tid] = ~0ull; }

    // A: convert x half-rows to bf16 SW128 + half norms (all 256 threads)
    {
        const float4* gx = (const float4*)(x +
            ((size_t)blockIdx.x * M_TILE + row) * D_DIM + half * 32);
        double sa = 0.0;
#pragma unroll
        for (int j = 0; j < 8; j++) {
            float4 v = gx[j];
            sa += (double)__fmul_rn(v.x, v.x); sa += (double)__fmul_rn(v.y, v.y);
            sa += (double)__fmul_rn(v.z, v.z); sa += (double)__fmul_rn(v.w, v.w);
            __nv_bfloat162 p0 = __floats2bfloat162_rn(v.x, v.y);
            __nv_bfloat162 p1 = __floats2bfloat162_rn(v.z, v.w);
            u32 base = (u32)row * 128 + half * 64 + j * 8;
            *(u32*)(smem + SM_A + sw128(base))     = *(u32*)&p0;
            *(u32*)(smem + SM_A + sw128(base + 4)) = *(u32*)&p1;
        }
        sand[tid] = sa;
    }
    __syncthreads();
    if (tid < M_TILE) san[tid] = (float)(sand[tid] + sand[tid + 128]);
    __syncthreads();

    // ---- screening: each warp handles rows [wrow, wrow+16) x 512 codes ----
    {
        u32 af[4][4];
        {
            int r    = (lane & 7) + ((lane & 8) ? 8 : 0);
            int hh   = (lane >> 4) & 1;
            u32 abase = (u32)(wrow + r) * 128 + hh * 16;
#pragma unroll
            for (int ks = 0; ks < 4; ks++)
                ldsm_x4(af[ks][0], af[ks][1], af[ks][2], af[ks][3],
                        sb + SM_A + sw128(abase + ks * 32));
        }
        const u32 bbase = (u32)(lane & 7) * 128 + ((lane >> 3) & 1) * 16;
        const int r0 = wrow + (lane >> 2);
        const int nlo = (lane & 3) * 2;

        // Phase 1: true row screen minima
        float tb0 = 3.4e38f, tb1 = 3.4e38f;
#pragma unroll 4
        for (int tile = 0; tile < 64; tile++) {
            float c0 = 0.f, c1 = 0.f, c2 = 0.f, c3 = 0.f;
            u32 tb_off = (u32)tile * 8 * 128;
#pragma unroll
            for (int ks = 0; ks < 4; ks++) {
                u32 b0, b1;
                ldsm_x2(b0, b1, sb + SM_B + sw128(tb_off + bbase + ks * 32));
                mma16816(c0, c1, c2, c3,
                         af[ks][0], af[ks][1], af[ks][2], af[ks][3], b0, b1);
            }
            int k0 = tile * 8 + nlo;
            float cn0 = scn[k0], cn1 = scn[k0 + 1];
            tb0 = fminf(tb0, fminf(__fmaf_rn(-2.f, c0, cn0),
                                   __fmaf_rn(-2.f, c1, cn1)));
            tb1 = fminf(tb1, fminf(__fmaf_rn(-2.f, c2, cn0),
                                   __fmaf_rn(-2.f, c3, cn1)));
        }
        tb0 = fminf(tb0, __shfl_xor_sync(0xFFFFFFFFu, tb0, 1));
        tb0 = fminf(tb0, __shfl_xor_sync(0xFFFFFFFFu, tb0, 2));
        tb1 = fminf(tb1, __shfl_xor_sync(0xFFFFFFFFu, tb1, 1));
        tb1 = fminf(tb1, __shfl_xor_sync(0xFFFFFFFFu, tb1, 2));
        const float thr0 = tb0 + EPS, thr1 = tb1 + EPS;

        // Phase 2: recompute, push candidates vs fixed thresholds
#pragma unroll 4
        for (int tile = 0; tile < 64; tile++) {
            float c0 = 0.f, c1 = 0.f, c2 = 0.f, c3 = 0.f;
            u32 tb_off = (u32)tile * 8 * 128;
#pragma unroll
            for (int ks = 0; ks < 4; ks++) {
                u32 b0, b1;
                ldsm_x2(b0, b1, sb + SM_B + sw128(tb_off + bbase + ks * 32));
                mma16816(c0, c1, c2, c3,
                         af[ks][0], af[ks][1], af[ks][2], af[ks][3], b0, b1);
            }
            int k0 = tile * 8 + nlo;
            float cn0 = scn[k0], cn1 = scn[k0 + 1];
            float t00 = __fmaf_rn(-2.f, c0, cn0);
            float t01 = __fmaf_rn(-2.f, c1, cn1);
            float t10 = __fmaf_rn(-2.f, c2, cn0);
            float t11 = __fmaf_rn(-2.f, c3, cn1);
            if (t00 < thr0) {
                int p = atomicAdd(&scnt[r0], 1);
                if (p < MAXC) scand[r0 * MAXC + p] = k0;
            }
            if (t01 < thr0) {
                int p = atomicAdd(&scnt[r0], 1);
                if (p < MAXC) scand[r0 * MAXC + p] = k0 + 1;
            }
            if (t10 < thr1) {
                int p = atomicAdd(&scnt[r0 + 8], 1);
                if (p < MAXC) scand[(r0 + 8) * MAXC + p] = k0;
            }
            if (t11 < thr1) {
                int p = atomicAdd(&scnt[r0 + 8], 1);
                if (p < MAXC) scand[(r0 + 8) * MAXC + p] = k0 + 1;
            }
        }
    }
    __syncthreads();

    // ---- exact rescore: pair-split candidates, u64-key argmin merge ----
    const int vid = blockIdx.x * M_TILE + row;
    const float4* xr = (const float4*)(x + (size_t)vid * D_DIM);
    {
        const float A = san[row];
        int nc = scnt[row];
        if (nc > MAXC) {                 // overflow: split full exact scan
            for (int k = half; k < K_CODES; k += 2) {
                float s = exact_score(cb, xr, A, scn[k], k);
                atomicMin(&skey[row], ((u64)__float_as_uint(s) << 32) | (u32)k);
            }
        } else {
            const int* cl = scand + row * MAXC;
            for (int i = half; i < nc; i += 2) {
                int k = cl[i];
                float s = exact_score(cb, xr, A, scn[k], k);
                // s > 0 always (dist^2 ~ 64): float bits order == value order.
                atomicMin(&skey[row], ((u64)__float_as_uint(s) << 32) | (u32)k);
            }
        }
    }
    __syncthreads();

    const int bi = (int)(u32)skey[row];
    if (half == 0) {
        outidx[vid] = (float)bi;
        atomicAdd(&g_hist[bi], 1);
    }

    // ---- epilogue: 2 threads/row, 32 floats each ----
    // quantized_st = x + (q - x); SSE of (q - x)^2.
    // outq is d_out+1 (odd float offset): scalar 32-bit stores only.
    float sse = 0.f;
    {
        const float4* qr = (const float4*)(cb + bi * D_DIM) + half * 8;
        const float4* xh = xr + half * 8;
        float* o = outq + (size_t)vid * D_DIM + half * 32;
#pragma unroll
        for (int j = 0; j < 8; j++) {
            float4 qv = qr[j], xv = xh[j];
            float d0 = __fadd_rn(qv.x, -xv.x), d1 = __fadd_rn(qv.y, -xv.y);
            float d2 = __fadd_rn(qv.z, -xv.z), d3 = __fadd_rn(qv.w, -xv.w);
            sse += d0 * d0 + d1 * d1 + d2 * d2 + d3 * d3;
            o[4 * j]     = __fadd_rn(xv.x, d0);
            o[4 * j + 1] = __fadd_rn(xv.y, d1);
            o[4 * j + 2] = __fadd_rn(xv.z, d2);
            o[4 * j + 3] = __fadd_rn(xv.w, d3);
        }
    }

    // Block-reduce SSE -> one double atomic per CTA
#pragma unroll
    for (int o = 16; o > 0; o >>= 1)
        sse += __shfl_xor_sync(0xFFFFFFFFu, sse, o);
    if ((tid & 31) == 0) sred[tid >> 5] = (double)sse;
    __syncthreads();
    if (tid == 0) {
        double s = 0.0;
#pragma unroll
        for (int w = 0; w < 8; w++) s += sred[w];
        atomicAdd(&g_sse, s);
    }
}

// ---------------------------------------------------------------------------
// Finalize: loss + perplexity; self-reset accumulators for graph replay.
// ---------------------------------------------------------------------------
__global__ void vq_final(float* __restrict__ out, int nd, int n) {
    int t = threadIdx.x;  // 512
    __shared__ double ssum;
    __shared__ float red[16];

    int h = g_hist[t];
    g_hist[t] = 0;                         // reset for next replay
    if (t == 0) { ssum = g_sse; g_sse = 0.0; }

    float p = (float)h / (float)n;
    float e = p * logf(p + 1e-10f);
#pragma unroll
    for (int o = 16; o > 0; o >>= 1)
        e += __shfl_xor_sync(0xFFFFFFFFu, e, o);
    if ((t & 31) == 0) red[t >> 5] = e;
    __syncthreads();
    if (t < 16) {
        float v = red[t];
#pragma unroll
        for (int o = 8; o > 0; o >>= 1)
            v += __shfl_xor_sync(0xFFFFu, v, o);
        if (t == 0) {
            out[1 + nd] = expf(-v);
            float m = (float)(ssum / (double)nd);
            out[0] = m + 0.25f * m;
        }
    }
}

// ---------------------------------------------------------------------------
extern "C" void kernel_launch(void* const* d_in, const int* in_sizes, int n_in,
                              void* d_out, int out_size) {
    const float* x  = (const float*)d_in[0];
    const float* cb = (const float*)d_in[1];
    float* out = (float*)d_out;

    int nd = in_sizes[0];   // 4194304
    int n  = nd / D_DIM;    // 65536

    cudaFuncSetAttribute(vq_main, cudaFuncAttributeMaxDynamicSharedMemorySize,
                         SMEM_SZ);

    vq_prep<<<64, 256>>>(cb);
    vq_main<<<TILES, TPB, SMEM_SZ>>>(x, cb, out + 1, out + 2 + nd);
    vq_final<<<1, K_CODES>>>(out, nd, n);
}